// round 9
// baseline (speedup 1.0000x reference)
#include <cuda_runtime.h>
#include <cuda_fp16.h>

#define B_  4
#define Q_  10000
#define H_  8
#define D_  32
#define L_  4
#define P_  4
#define S_  21760
#define BQH (B_ * Q_ * H_)

// Padded fp16 mirror, head-major. Levels 1-3 stored twice (parity mirrors,
// shifted one pixel) so the bilinear x-pair reads one aligned 128B line.
//   L0:        130x130 = 16900 @ 0            (single copy, wq=130)
//   L1 m0/m1:  66x68   = 4488  @ 16900/21388  (wq=68)
//   L2 m0/m1:  34x36   = 1224  @ 25876/27100  (wq=36)
//   L3 m0/m1:  18x20   = 360   @ 28324/28684  (wq=20)
// Unwritten slots stay zero (device globals zero-initialized, never written)
// -> matches grid_sample zero padding exactly.
#define PIX_TOT 29044

__device__ uint4 g_vh[(size_t)B_ * H_ * PIX_TOT * 4];   // 59.5 MB

// ---------------------------------------------------------------------------
// Pre-pass: value [B,S,H,D] fp32 -> padded fp16 mirrors (interior only).
// One thread per 8 channels: 32B read, 16B store (STG.128).
// ---------------------------------------------------------------------------
__global__ __launch_bounds__(256)
void convert_kernel(const float* __restrict__ value)
{
    const int total = B_ * H_ * S_ * (D_ / 8);      // 2,785,280
    int idx = blockIdx.x * blockDim.x + threadIdx.x;
    if (idx >= total) return;

    const int dg = idx & 3;             // 8-channel group
    const int s  = (idx >> 2) % S_;
    const int bh = (idx >> 2) / S_;
    const int h  = bh & (H_ - 1);
    const int b  = bh >> 3;

    const float* src = value + (((size_t)b * S_ + s) * H_ + h) * D_ + dg * 8;
    const float4 v0 = *reinterpret_cast<const float4*>(src);
    const float4 v1 = *reinterpret_cast<const float4*>(src + 4);

    uint4 packed;
    {
        __half2 a = __floats2half2_rn(v0.x, v0.y);
        __half2 c = __floats2half2_rn(v0.z, v0.w);
        __half2 e = __floats2half2_rn(v1.x, v1.y);
        __half2 f = __floats2half2_rn(v1.z, v1.w);
        packed.x = *reinterpret_cast<const unsigned*>(&a);
        packed.y = *reinterpret_cast<const unsigned*>(&c);
        packed.z = *reinterpret_cast<const unsigned*>(&e);
        packed.w = *reinterpret_cast<const unsigned*>(&f);
    }

    const size_t bhbase = (size_t)bh * PIX_TOT;

    int p0, p1 = -1;
    if (s < 16384)      { int t = s;         int r = t >> 7, c = t & 127;
                          p0 = 0     + (r + 1) * 130 + c + 1; }
    else if (s < 20480) { int t = s - 16384; int r = t >> 6, c = t & 63;
                          p0 = 16900 + (r + 1) * 68 + c + 1;
                          p1 = 21388 + (r + 1) * 68 + c + 2; }
    else if (s < 21504) { int t = s - 20480; int r = t >> 5, c = t & 31;
                          p0 = 25876 + (r + 1) * 36 + c + 1;
                          p1 = 27100 + (r + 1) * 36 + c + 2; }
    else                { int t = s - 21504; int r = t >> 4, c = t & 15;
                          p0 = 28324 + (r + 1) * 20 + c + 1;
                          p1 = 28684 + (r + 1) * 20 + c + 2; }

    g_vh[(bhbase + p0) * 4 + dg] = packed;
    if (p1 >= 0) g_vh[(bhbase + p1) * 4 + dg] = packed;
}

// ---------------------------------------------------------------------------
// Main kernel. One warp per (b,q,h), scheduled (b,h)-MAJOR: all warps of a
// block (and of a launch wave) share one 1.86MB per-head mirror slice, so
// gathers hit L1/L2 far more often. I/O offsets are recomputed to the
// original (b,q,h) order.
// Lane map: bits3-4 = sample slot sm, bit2 = x-corner cx, bits0-1 = dg.
// ---------------------------------------------------------------------------
__device__ __forceinline__ __half2 u2h2(unsigned u) {
    return *reinterpret_cast<const __half2*>(&u);
}

__device__ __forceinline__ __half2 h2shfl_xor(__half2 v, int ofs) {
    unsigned u = *reinterpret_cast<unsigned*>(&v);
    u = __shfl_xor_sync(0xffffffffu, u, ofs);
    return u2h2(u);
}

struct Meta {
    int offA;           // uint4 offset of row y0 (row y0+1 = compile-time imm)
    __half2 c0, c1;     // broadcast weights
};

template <int LVL>
__device__ __forceinline__ Meta level_meta(float locv, float awv,
                                           int sm, int cx, float ax, float bx)
{
    constexpr int HHs[L_]   = {128, 64, 32, 16};
    constexpr int WWs[L_]   = {128, 64, 32, 16};
    constexpr int BASEs[L_] = {0, 16900, 25876, 28324};
    constexpr int MSs[L_]   = {0, 4489, 1225, 361};   // mirror stride + 1
    constexpr int WQs[L_]   = {130, 68, 36, 20};

    const float xl = __shfl_sync(0xffffffffu, locv, 8 * LVL + 2 * sm);
    const float yl = __shfl_sync(0xffffffffu, locv, 8 * LVL + 2 * sm + 1);
    const float wa = __shfl_sync(0xffffffffu, awv,  4 * LVL + sm);

    const float x = fmaf(xl, (float)WWs[LVL], -0.5f);
    const float y = fmaf(yl, (float)HHs[LVL], -0.5f);
    const int ix0 = __float2int_rd(x);
    const int iy0 = __float2int_rd(y);
    const float fx = x - (float)ix0;
    const float fy = y - (float)iy0;

    const float cwx = fmaf(fx, ax, bx) * wa;
    const float cw1 = cwx * fy;
    const float cw0 = cwx - cw1;

    const int m = (LVL == 0) ? 0 : ((ix0 & 1) ^ 1);
    const int pix = BASEs[LVL] + m * MSs[LVL]
                  + (iy0 + 1) * WQs[LVL] + ix0 + 1 + cx;

    Meta r;
    r.offA = pix * 4;
    r.c0 = __float2half2_rn(cw0);
    r.c1 = __float2half2_rn(cw1);
    return r;
}

// One level: two row loads (imm-offset apart) weighted into half2 partials.
template <int LVL, bool FIRST>
__device__ __forceinline__ void do_level(const uint4* __restrict__ base,
                                         const Meta& m,
                                         __half2& p0, __half2& p1,
                                         __half2& p2, __half2& p3)
{
    constexpr int WQs[L_] = {130, 68, 36, 20};
    const uint4* pa = base + m.offA;
    const uint4 rA = pa[0];
    const uint4 rB = pa[WQs[LVL] * 4];   // compile-time immediate offset

    if (FIRST) {
        p0 = __hmul2(u2h2(rA.x), m.c0);
        p1 = __hmul2(u2h2(rA.y), m.c0);
        p2 = __hmul2(u2h2(rA.z), m.c0);
        p3 = __hmul2(u2h2(rA.w), m.c0);
    } else {
        p0 = __hfma2(u2h2(rA.x), m.c0, p0);
        p1 = __hfma2(u2h2(rA.y), m.c0, p1);
        p2 = __hfma2(u2h2(rA.z), m.c0, p2);
        p3 = __hfma2(u2h2(rA.w), m.c0, p3);
    }
    p0 = __hfma2(u2h2(rB.x), m.c1, p0);
    p1 = __hfma2(u2h2(rB.y), m.c1, p1);
    p2 = __hfma2(u2h2(rB.z), m.c1, p2);
    p3 = __hfma2(u2h2(rB.w), m.c1, p3);
}

__global__ __launch_bounds__(256)
void msda_kernel(const float* __restrict__ loc,
                 const float* __restrict__ aw,
                 float* __restrict__ out)
{
    // (b,h)-major warp schedule: w = bh * Q + q.
    const int w    = (blockIdx.x * blockDim.x + threadIdx.x) >> 5;
    const int lane = threadIdx.x & 31;

    const int bh = w / Q_;
    const int q  = w - bh * Q_;
    const int h  = bh & (H_ - 1);
    const int b  = bh >> 3;
    const int wo = (b * Q_ + q) * H_ + h;   // original (b,q,h) flat index

    // Streamed metadata: evict-first so it doesn't pollute L1 gather lines.
    const float locv = __ldcs(loc + (size_t)wo * (L_ * P_ * 2) + lane);
    const float awv  = (lane < L_ * P_)
                     ? __ldcs(aw + (size_t)wo * (L_ * P_) + lane) : 0.0f;

    const int sm = lane >> 3;
    const int cx = (lane >> 2) & 1;
    const int dg = lane & 3;

    const float ax = cx ? 1.0f : -1.0f;
    const float bx = cx ? 0.0f : 1.0f;

    const uint4* base = g_vh + (size_t)bh * (PIX_TOT * 4) + dg;

    // Group 0: levels 0,1 in half2 partials q0-3.
    __half2 g0, g1, g2, g3;
    {
        const Meta m0 = level_meta<0>(locv, awv, sm, cx, ax, bx);
        do_level<0, true >(base, m0, g0, g1, g2, g3);
        const Meta m1 = level_meta<1>(locv, awv, sm, cx, ax, bx);
        do_level<1, false>(base, m1, g0, g1, g2, g3);
    }

    // Group 1: levels 2,3 in half2 partials p0-3.
    __half2 p0, p1, p2, p3;
    {
        const Meta m2 = level_meta<2>(locv, awv, sm, cx, ax, bx);
        do_level<2, true >(base, m2, p0, p1, p2, p3);
        const Meta m3 = level_meta<3>(locv, awv, sm, cx, ax, bx);
        do_level<3, false>(base, m3, p0, p1, p2, p3);
    }

    // Combine groups (half2).
    p0 = __hadd2(p0, g0);
    p1 = __hadd2(p1, g1);
    p2 = __hadd2(p2, g2);
    p3 = __hadd2(p3, g3);

    // Corner reduction (xor 4) packed in half2.
    p0 = __hadd2(p0, h2shfl_xor(p0, 4));
    p1 = __hadd2(p1, h2shfl_xor(p1, 4));
    p2 = __hadd2(p2, h2shfl_xor(p2, 4));
    p3 = __hadd2(p3, h2shfl_xor(p3, 4));

    // To fp32 once.
    float accf[8];
    {
        float2 t;
        t = __half22float2(p0); accf[0] = t.x; accf[1] = t.y;
        t = __half22float2(p1); accf[2] = t.x; accf[3] = t.y;
        t = __half22float2(p2); accf[4] = t.x; accf[5] = t.y;
        t = __half22float2(p3); accf[6] = t.x; accf[7] = t.y;
    }

    // Sample-slot reduction (xor 8, 16) in fp32.
#pragma unroll
    for (int ofs = 8; ofs <= 16; ofs <<= 1) {
#pragma unroll
        for (int i = 0; i < 8; i++)
            accf[i] += __shfl_xor_sync(0xffffffffu, accf[i], ofs);
    }

    if (lane < 4) {
        float* o = out + (size_t)wo * D_ + dg * 8;
        __stcs(reinterpret_cast<float4*>(o),
               make_float4(accf[0], accf[1], accf[2], accf[3]));
        __stcs(reinterpret_cast<float4*>(o + 4),
               make_float4(accf[4], accf[5], accf[6], accf[7]));
    }
}

extern "C" void kernel_launch(void* const* d_in, const int* in_sizes, int n_in,
                              void* d_out, int out_size)
{
    const float* value = (const float*)d_in[0];
    const float* loc   = (const float*)d_in[3];
    const float* aw    = (const float*)d_in[4];
    float* out = (float*)d_out;

    const int conv_total = B_ * H_ * S_ * (D_ / 8);
    convert_kernel<<<(conv_total + 255) / 256, 256>>>(value);

    const int total_threads = BQH * 32;
    msda_kernel<<<(total_threads + 255) / 256, 256>>>(loc, aw, out);
}

// round 10
// speedup vs baseline: 1.0924x; 1.0924x over previous
#include <cuda_runtime.h>
#include <cuda_fp16.h>

#define B_  4
#define Q_  10000
#define H_  8
#define D_  32
#define L_  4
#define P_  4
#define S_  21760
#define BQH (B_ * Q_ * H_)

// Padded fp16 mirror, head-major. Levels 1-3 stored twice (parity mirrors,
// shifted one pixel) so the bilinear x-pair reads one aligned 128B line.
//   L0:        130x130 = 16900 @ 0            (single copy, wq=130)
//   L1 m0/m1:  66x68   = 4488  @ 16900/21388  (wq=68)
//   L2 m0/m1:  34x36   = 1224  @ 25876/27100  (wq=36)
//   L3 m0/m1:  18x20   = 360   @ 28324/28684  (wq=20)
// Unwritten slots stay zero (device globals zero-initialized, never written)
// -> matches grid_sample zero padding exactly.
#define PIX_TOT 29044

__device__ uint4 g_vh[(size_t)B_ * H_ * PIX_TOT * 4];   // 59.5 MB

// ---------------------------------------------------------------------------
// Pre-pass (per-batch chunk): value [B,S,H,D] fp32 -> padded fp16 mirrors.
// One thread per 8 channels: 32B read, 16B store (STG.128).
// ---------------------------------------------------------------------------
__global__ __launch_bounds__(256)
void convert_kernel(const float* __restrict__ value, int b)
{
    const int total = H_ * S_ * (D_ / 8);           // 696,320 per batch
    int idx = blockIdx.x * blockDim.x + threadIdx.x;
    if (idx >= total) return;

    const int dg = idx & 3;             // 8-channel group
    const int s  = (idx >> 2) % S_;
    const int h  = (idx >> 2) / S_;
    const int bh = b * H_ + h;

    const float* src = value + (((size_t)b * S_ + s) * H_ + h) * D_ + dg * 8;
    const float4 v0 = *reinterpret_cast<const float4*>(src);
    const float4 v1 = *reinterpret_cast<const float4*>(src + 4);

    uint4 packed;
    {
        __half2 a = __floats2half2_rn(v0.x, v0.y);
        __half2 c = __floats2half2_rn(v0.z, v0.w);
        __half2 e = __floats2half2_rn(v1.x, v1.y);
        __half2 f = __floats2half2_rn(v1.z, v1.w);
        packed.x = *reinterpret_cast<const unsigned*>(&a);
        packed.y = *reinterpret_cast<const unsigned*>(&c);
        packed.z = *reinterpret_cast<const unsigned*>(&e);
        packed.w = *reinterpret_cast<const unsigned*>(&f);
    }

    const size_t bhbase = (size_t)bh * PIX_TOT;

    int p0, p1 = -1;
    if (s < 16384)      { int t = s;         int r = t >> 7, c = t & 127;
                          p0 = 0     + (r + 1) * 130 + c + 1; }
    else if (s < 20480) { int t = s - 16384; int r = t >> 6, c = t & 63;
                          p0 = 16900 + (r + 1) * 68 + c + 1;
                          p1 = 21388 + (r + 1) * 68 + c + 2; }
    else if (s < 21504) { int t = s - 20480; int r = t >> 5, c = t & 31;
                          p0 = 25876 + (r + 1) * 36 + c + 1;
                          p1 = 27100 + (r + 1) * 36 + c + 2; }
    else                { int t = s - 21504; int r = t >> 4, c = t & 15;
                          p0 = 28324 + (r + 1) * 20 + c + 1;
                          p1 = 28684 + (r + 1) * 20 + c + 2; }

    g_vh[(bhbase + p0) * 4 + dg] = packed;
    if (p1 >= 0) g_vh[(bhbase + p1) * 4 + dg] = packed;
}

// ---------------------------------------------------------------------------
// Main kernel (per-batch chunk). One warp per (b,q,h), (b,q,h)-major order
// (R8 schedule — R9 showed remapping scatters the metadata streams).
// Lane map: bits3-4 = sample slot sm, bit2 = x-corner cx, bits0-1 = dg.
// ---------------------------------------------------------------------------
__device__ __forceinline__ __half2 u2h2(unsigned u) {
    return *reinterpret_cast<const __half2*>(&u);
}

__device__ __forceinline__ __half2 h2shfl_xor(__half2 v, int ofs) {
    unsigned u = *reinterpret_cast<unsigned*>(&v);
    u = __shfl_xor_sync(0xffffffffu, u, ofs);
    return u2h2(u);
}

struct Meta {
    int offA;           // uint4 offset of row y0 (row y0+1 = compile-time imm)
    __half2 c0, c1;     // broadcast weights
};

template <int LVL>
__device__ __forceinline__ Meta level_meta(float locv, float awv,
                                           int sm, int cx, float ax, float bx)
{
    constexpr int HHs[L_]   = {128, 64, 32, 16};
    constexpr int WWs[L_]   = {128, 64, 32, 16};
    constexpr int BASEs[L_] = {0, 16900, 25876, 28324};
    constexpr int MSs[L_]   = {0, 4489, 1225, 361};   // mirror stride + 1
    constexpr int WQs[L_]   = {130, 68, 36, 20};

    const float xl = __shfl_sync(0xffffffffu, locv, 8 * LVL + 2 * sm);
    const float yl = __shfl_sync(0xffffffffu, locv, 8 * LVL + 2 * sm + 1);
    const float wa = __shfl_sync(0xffffffffu, awv,  4 * LVL + sm);

    const float x = fmaf(xl, (float)WWs[LVL], -0.5f);
    const float y = fmaf(yl, (float)HHs[LVL], -0.5f);
    const int ix0 = __float2int_rd(x);
    const int iy0 = __float2int_rd(y);
    const float fx = x - (float)ix0;
    const float fy = y - (float)iy0;

    const float cwx = fmaf(fx, ax, bx) * wa;
    const float cw1 = cwx * fy;
    const float cw0 = cwx - cw1;

    const int m = (LVL == 0) ? 0 : ((ix0 & 1) ^ 1);
    const int pix = BASEs[LVL] + m * MSs[LVL]
                  + (iy0 + 1) * WQs[LVL] + ix0 + 1 + cx;

    Meta r;
    r.offA = pix * 4;
    r.c0 = __float2half2_rn(cw0);
    r.c1 = __float2half2_rn(cw1);
    return r;
}

template <int LVL, bool FIRST>
__device__ __forceinline__ void do_level(const uint4* __restrict__ base,
                                         const Meta& m,
                                         __half2& p0, __half2& p1,
                                         __half2& p2, __half2& p3)
{
    constexpr int WQs[L_] = {130, 68, 36, 20};
    const uint4* pa = base + m.offA;
    const uint4 rA = pa[0];
    const uint4 rB = pa[WQs[LVL] * 4];   // compile-time immediate offset

    if (FIRST) {
        p0 = __hmul2(u2h2(rA.x), m.c0);
        p1 = __hmul2(u2h2(rA.y), m.c0);
        p2 = __hmul2(u2h2(rA.z), m.c0);
        p3 = __hmul2(u2h2(rA.w), m.c0);
    } else {
        p0 = __hfma2(u2h2(rA.x), m.c0, p0);
        p1 = __hfma2(u2h2(rA.y), m.c0, p1);
        p2 = __hfma2(u2h2(rA.z), m.c0, p2);
        p3 = __hfma2(u2h2(rA.w), m.c0, p3);
    }
    p0 = __hfma2(u2h2(rB.x), m.c1, p0);
    p1 = __hfma2(u2h2(rB.y), m.c1, p1);
    p2 = __hfma2(u2h2(rB.z), m.c1, p2);
    p3 = __hfma2(u2h2(rB.w), m.c1, p3);
}

__global__ __launch_bounds__(256)
void msda_kernel(const float* __restrict__ loc,
                 const float* __restrict__ aw,
                 float* __restrict__ out,
                 int wbase)
{
    const int warp = wbase + ((blockIdx.x * blockDim.x + threadIdx.x) >> 5);
    const int lane = threadIdx.x & 31;

    const int h  = warp & (H_ - 1);
    const int bq = warp >> 3;
    const int b  = bq / Q_;

    const float locv = loc[(size_t)warp * (L_ * P_ * 2) + lane];
    const float awv  = (lane < L_ * P_) ? aw[(size_t)warp * (L_ * P_) + lane] : 0.0f;

    const int sm = lane >> 3;
    const int cx = (lane >> 2) & 1;
    const int dg = lane & 3;

    const float ax = cx ? 1.0f : -1.0f;
    const float bx = cx ? 0.0f : 1.0f;

    const uint4* base = g_vh + ((size_t)(b * H_ + h)) * (PIX_TOT * 4) + dg;

    // Group 0: levels 0,1 in half2 partials g0-3.
    __half2 g0, g1, g2, g3;
    {
        const Meta m0 = level_meta<0>(locv, awv, sm, cx, ax, bx);
        do_level<0, true >(base, m0, g0, g1, g2, g3);
        const Meta m1 = level_meta<1>(locv, awv, sm, cx, ax, bx);
        do_level<1, false>(base, m1, g0, g1, g2, g3);
    }

    // Group 1: levels 2,3 in half2 partials p0-3.
    __half2 p0, p1, p2, p3;
    {
        const Meta m2 = level_meta<2>(locv, awv, sm, cx, ax, bx);
        do_level<2, true >(base, m2, p0, p1, p2, p3);
        const Meta m3 = level_meta<3>(locv, awv, sm, cx, ax, bx);
        do_level<3, false>(base, m3, p0, p1, p2, p3);
    }

    // Combine groups (half2).
    p0 = __hadd2(p0, g0);
    p1 = __hadd2(p1, g1);
    p2 = __hadd2(p2, g2);
    p3 = __hadd2(p3, g3);

    // Corner reduction (xor 4) packed in half2.
    p0 = __hadd2(p0, h2shfl_xor(p0, 4));
    p1 = __hadd2(p1, h2shfl_xor(p1, 4));
    p2 = __hadd2(p2, h2shfl_xor(p2, 4));
    p3 = __hadd2(p3, h2shfl_xor(p3, 4));

    // To fp32 once.
    float accf[8];
    {
        float2 t;
        t = __half22float2(p0); accf[0] = t.x; accf[1] = t.y;
        t = __half22float2(p1); accf[2] = t.x; accf[3] = t.y;
        t = __half22float2(p2); accf[4] = t.x; accf[5] = t.y;
        t = __half22float2(p3); accf[6] = t.x; accf[7] = t.y;
    }

    // Sample-slot reduction (xor 8, 16) in fp32.
#pragma unroll
    for (int ofs = 8; ofs <= 16; ofs <<= 1) {
#pragma unroll
        for (int i = 0; i < 8; i++)
            accf[i] += __shfl_xor_sync(0xffffffffu, accf[i], ofs);
    }

    if (lane < 4) {
        float* o = out + (size_t)warp * D_ + dg * 8;
        *reinterpret_cast<float4*>(o)     = make_float4(accf[0], accf[1], accf[2], accf[3]);
        *reinterpret_cast<float4*>(o + 4) = make_float4(accf[4], accf[5], accf[6], accf[7]);
    }
}

// ---------------------------------------------------------------------------
// Launch: 4 per-batch chunks software-pipelined across two streams.
//   legacy: conv0 conv1 conv2 conv3
//   s2    :       main0 main1 main2 main3   (main_b waits only on conv_b)
// Streams/events are created lazily on the FIRST call (the correctness run,
// which happens before graph capture); the captured work is identical every
// call. Event record/wait edges are the documented multi-stream capture
// pattern; s2 joins back to the legacy stream before return.
// ---------------------------------------------------------------------------
extern "C" void kernel_launch(void* const* d_in, const int* in_sizes, int n_in,
                              void* d_out, int out_size)
{
    const float* value = (const float*)d_in[0];
    const float* loc   = (const float*)d_in[3];
    const float* aw    = (const float*)d_in[4];
    float* out = (float*)d_out;

    static cudaStream_t s2 = nullptr;
    static cudaEvent_t evc[B_];
    static cudaEvent_t evj = nullptr;
    if (s2 == nullptr) {
        cudaStreamCreateWithFlags(&s2, cudaStreamNonBlocking);
        for (int i = 0; i < B_; i++)
            cudaEventCreateWithFlags(&evc[i], cudaEventDisableTiming);
        cudaEventCreateWithFlags(&evj, cudaEventDisableTiming);
    }

    const int conv_total = H_ * S_ * (D_ / 8);           // per batch
    const int conv_grid  = (conv_total + 255) / 256;
    const int main_grid  = (Q_ * H_ * 32) / 256;         // 10000 blocks/batch

    for (int b = 0; b < B_; b++) {
        convert_kernel<<<conv_grid, 256, 0, (cudaStream_t)0>>>(value, b);
        cudaEventRecord(evc[b], (cudaStream_t)0);
        cudaStreamWaitEvent(s2, evc[b], 0);
        msda_kernel<<<main_grid, 256, 0, s2>>>(loc, aw, out, b * Q_ * H_);
    }

    cudaEventRecord(evj, s2);
    cudaStreamWaitEvent((cudaStream_t)0, evj, 0);
}